// round 1
// baseline (speedup 1.0000x reference)
#include <cuda_runtime.h>
#include <cuda_bf16.h>
#include <math.h>

// Problem constants (match reference_code)
#define NU 100000
#define NI 100000
#define NE 300000
#define S 128
#define MDIM 512          // GRU input dim
#define G3 384            // 3*S gate rows
#define NROWS (NU + NI)   // 200000 total GRU rows (users then items)

// ---- scratch (static device globals; no runtime allocation) ----
__device__ int   d_lastU[NU];
__device__ int   d_lastV[NI];
__device__ float d_X [(size_t)NROWS * MDIM];   // gathered mail per node (winning edge), 409.6 MB
__device__ float d_G1[(size_t)NROWS * G3];     // X @ Wi^T
__device__ float d_G2[(size_t)NROWS * G3];     // H @ Wh^T

// ---------------------------------------------------------------------------
// K0: init last-edge ids to -1
__global__ void k_init_last() {
    int i = blockIdx.x * blockDim.x + threadIdx.x;
    if (i < NU) d_lastU[i] = -1;
    if (i < NI) d_lastV[i] = -1;
}

// K1: segment_max of edge id per src (users) and per dst (items)
__global__ void k_scan_edges(const int* __restrict__ src, const int* __restrict__ dst) {
    int i = blockIdx.x * blockDim.x + threadIdx.x;
    if (i < NE) {
        atomicMax(&d_lastU[src[i]], i);
        atomicMax(&d_lastV[dst[i]], i);
    }
}

// K2: build X rows for winning edges only.
// user row r (<NU):   mail_r = [ sj[dst[le]], si[r], cos(t*freq), e[le] ]
// item row r-NU:      mail_f = [ si[src[le]], sj[v], cos(t*freq), e[le] ]
__global__ void k_build_x(const float* __restrict__ si, const float* __restrict__ sj,
                          const float* __restrict__ t,  const float* __restrict__ efeat,
                          const int* __restrict__ src,  const int* __restrict__ dst,
                          const float* __restrict__ freq) {
    int r = blockIdx.x;
    int j = threadIdx.x;  // 0..127
    float* xr = d_X + (size_t)r * MDIM;
    if (r < NU) {
        int le = d_lastU[r];
        if (le < 0) {
            xr[j] = 0.f; xr[j + 128] = 0.f; xr[j + 256] = 0.f; xr[j + 384] = 0.f;
            return;
        }
        int dn = dst[le];
        xr[j]       = sj[(size_t)dn * S + j];
        xr[j + 128] = si[(size_t)r  * S + j];
        xr[j + 256] = cosf(t[le] * freq[j]);
        xr[j + 384] = efeat[(size_t)le * S + j];
    } else {
        int v = r - NU;
        int le = d_lastV[v];
        if (le < 0) {
            xr[j] = 0.f; xr[j + 128] = 0.f; xr[j + 256] = 0.f; xr[j + 384] = 0.f;
            return;
        }
        int sn = src[le];
        xr[j]       = si[(size_t)sn * S + j];
        xr[j + 128] = sj[(size_t)v  * S + j];
        xr[j + 256] = cosf(t[le] * freq[j]);
        xr[j + 384] = efeat[(size_t)le * S + j];
    }
}

// ---------------------------------------------------------------------------
// K3/K4: C[M,384] = A[M,K] @ B[384,K]^T   (fp32, 128x128x8 tiles, 8x8 microtile)
// A selection: use_X ? d_X : A_ext.   C selection: c_sel ? d_G2 : d_G1 (+row off).
__global__ __launch_bounds__(256, 2)
void k_sgemm_nt(const float* __restrict__ A_ext, int use_X,
                const float* __restrict__ B,
                int c_sel, int c_row_off, int Mrows, int K) {
    __shared__ float As[8][128];
    __shared__ float Bs[8][128];

    const float* A = use_X ? d_X : A_ext;
    float* C = (c_sel ? d_G2 : d_G1) + (size_t)c_row_off * G3;

    const int tid  = threadIdx.x;
    const int m0   = blockIdx.x * 128;
    const int n0   = blockIdx.y * 128;
    const int lrow = tid >> 1;           // 0..127
    const int lk   = (tid & 1) << 2;     // 0 or 4
    const int tx   = tid & 15;
    const int ty   = tid >> 4;

    float acc[8][8];
#pragma unroll
    for (int i = 0; i < 8; ++i)
#pragma unroll
        for (int j = 0; j < 8; ++j) acc[i][j] = 0.f;

    const bool a_ok = (m0 + lrow) < Mrows;
    const float* Aptr = A + (size_t)(m0 + lrow) * K + lk;
    const float* Bptr = B + (size_t)(n0 + lrow) * K + lk;

    for (int k0 = 0; k0 < K; k0 += 8) {
        float4 av = a_ok ? *(const float4*)(Aptr + k0) : make_float4(0.f, 0.f, 0.f, 0.f);
        float4 bv = *(const float4*)(Bptr + k0);
        As[lk + 0][lrow] = av.x; As[lk + 1][lrow] = av.y;
        As[lk + 2][lrow] = av.z; As[lk + 3][lrow] = av.w;
        Bs[lk + 0][lrow] = bv.x; Bs[lk + 1][lrow] = bv.y;
        Bs[lk + 2][lrow] = bv.z; Bs[lk + 3][lrow] = bv.w;
        __syncthreads();
#pragma unroll
        for (int kk = 0; kk < 8; ++kk) {
            float a[8], b[8];
            *(float4*)&a[0] = *(const float4*)&As[kk][ty * 8];
            *(float4*)&a[4] = *(const float4*)&As[kk][ty * 8 + 4];
            *(float4*)&b[0] = *(const float4*)&Bs[kk][tx * 8];
            *(float4*)&b[4] = *(const float4*)&Bs[kk][tx * 8 + 4];
#pragma unroll
            for (int i = 0; i < 8; ++i)
#pragma unroll
                for (int j = 0; j < 8; ++j)
                    acc[i][j] = fmaf(a[i], b[j], acc[i][j]);
        }
        __syncthreads();
    }

#pragma unroll
    for (int i = 0; i < 8; ++i) {
        int gr = m0 + ty * 8 + i;
        if (gr < Mrows) {
            float* cp = C + (size_t)gr * G3 + n0 + tx * 8;
            *(float4*)(cp)     = make_float4(acc[i][0], acc[i][1], acc[i][2], acc[i][3]);
            *(float4*)(cp + 4) = make_float4(acc[i][4], acc[i][5], acc[i][6], acc[i][7]);
        }
    }
}

// ---------------------------------------------------------------------------
// K5: GRU gate combine + output
__global__ void k_combine(const float* __restrict__ si, const float* __restrict__ sj,
                          const float* __restrict__ bi, const float* __restrict__ bh,
                          float* __restrict__ out) {
    int r = blockIdx.x;
    int j = threadIdx.x;  // 0..127
    const float* g1 = d_G1 + (size_t)r * G3;
    const float* g2 = d_G2 + (size_t)r * G3;

    float h = (r < NU) ? si[(size_t)r * S + j] : sj[(size_t)(r - NU) * S + j];

    float gir = g1[j]       + bi[j];
    float giz = g1[j + 128] + bi[j + 128];
    float gin = g1[j + 256] + bi[j + 256];
    float ghr = g2[j]       + bh[j];
    float ghz = g2[j + 128] + bh[j + 128];
    float ghn = g2[j + 256] + bh[j + 256];

    float rr = 1.f / (1.f + expf(-(gir + ghr)));
    float zz = 1.f / (1.f + expf(-(giz + ghz)));
    float nn = tanhf(gin + rr * ghn);

    out[(size_t)r * S + j] = (1.f - zz) * nn + zz * h;
}

// ---------------------------------------------------------------------------
extern "C" void kernel_launch(void* const* d_in, const int* in_sizes, int n_in,
                              void* d_out, int out_size) {
    const float* si   = (const float*)d_in[0];
    const float* sj   = (const float*)d_in[1];
    const float* t    = (const float*)d_in[2];
    const float* ef   = (const float*)d_in[3];
    const int*   src  = (const int*)d_in[4];
    const int*   dst  = (const int*)d_in[5];
    const float* Wi   = (const float*)d_in[6];
    const float* Wh   = (const float*)d_in[7];
    const float* bi   = (const float*)d_in[8];
    const float* bh   = (const float*)d_in[9];
    const float* freq = (const float*)d_in[10];
    float* out = (float*)d_out;

    // last-edge reduce
    k_init_last<<<(NU + 255) / 256, 256>>>();
    k_scan_edges<<<(NE + 255) / 256, 256>>>(src, dst);

    // gather winning mails into X
    k_build_x<<<NROWS, 128>>>(si, sj, t, ef, src, dst, freq);

    // G1 = X @ Wi^T   (M=200000, K=512)
    {
        dim3 grid((NROWS + 127) / 128, G3 / 128);
        k_sgemm_nt<<<grid, 256>>>(nullptr, 1, Wi, 0, 0, NROWS, MDIM);
    }
    // G2 = H @ Wh^T   (two launches: users then items; M=100000, K=128)
    {
        dim3 grid((NU + 127) / 128, G3 / 128);
        k_sgemm_nt<<<grid, 256>>>(si, 0, Wh, 1, 0,  NU, S);
        k_sgemm_nt<<<grid, 256>>>(sj, 0, Wh, 1, NU, NI, S);
    }

    // gates + output
    k_combine<<<NROWS, 128>>>(si, sj, bi, bh, out);
}

// round 2
// speedup vs baseline: 2.1589x; 2.1589x over previous
#include <cuda_runtime.h>
#include <cuda_bf16.h>
#include <math.h>
#include <stdint.h>

// Problem constants (match reference_code)
#define NU 100000
#define NI 100000
#define NE 300000
#define S 128
#define MDIM 512          // GRU input dim
#define G3 384            // 3*S gate rows
#define NROWS (NU + NI)   // 200000 total GRU rows (users then items)

// ---- scratch (static device globals; no runtime allocation) ----
__device__ int   d_lastU[NU];
__device__ int   d_lastV[NI];
__device__ float d_X [(size_t)NROWS * MDIM];   // gathered mail per node (winning edge)
__device__ float d_G1[(size_t)NROWS * G3];     // X @ Wi^T
__device__ float d_G2[(size_t)NROWS * G3];     // H @ Wh^T

// ---------------------------------------------------------------------------
__global__ void k_init_last() {
    int i = blockIdx.x * blockDim.x + threadIdx.x;
    if (i < NU) d_lastU[i] = -1;
    if (i < NI) d_lastV[i] = -1;
}

__global__ void k_scan_edges(const int* __restrict__ src, const int* __restrict__ dst) {
    int i = blockIdx.x * blockDim.x + threadIdx.x;
    if (i < NE) {
        atomicMax(&d_lastU[src[i]], i);
        atomicMax(&d_lastV[dst[i]], i);
    }
}

// K2: build X rows for winning edges only.
__global__ void k_build_x(const float* __restrict__ si, const float* __restrict__ sj,
                          const float* __restrict__ t,  const float* __restrict__ efeat,
                          const int* __restrict__ src,  const int* __restrict__ dst,
                          const float* __restrict__ freq) {
    int r = blockIdx.x;
    int j = threadIdx.x;  // 0..127
    float* xr = d_X + (size_t)r * MDIM;
    if (r < NU) {
        int le = d_lastU[r];
        if (le < 0) {
            xr[j] = 0.f; xr[j + 128] = 0.f; xr[j + 256] = 0.f; xr[j + 384] = 0.f;
            return;
        }
        int dn = dst[le];
        xr[j]       = sj[(size_t)dn * S + j];
        xr[j + 128] = si[(size_t)r  * S + j];
        xr[j + 256] = cosf(t[le] * freq[j]);
        xr[j + 384] = efeat[(size_t)le * S + j];
    } else {
        int v = r - NU;
        int le = d_lastV[v];
        if (le < 0) {
            xr[j] = 0.f; xr[j + 128] = 0.f; xr[j + 256] = 0.f; xr[j + 384] = 0.f;
            return;
        }
        int sn = src[le];
        xr[j]       = si[(size_t)sn * S + j];
        xr[j + 128] = sj[(size_t)v  * S + j];
        xr[j + 256] = cosf(t[le] * freq[j]);
        xr[j + 384] = efeat[(size_t)le * S + j];
    }
}

// ---------------------------------------------------------------------------
// tf32 helpers
__device__ __forceinline__ uint32_t f2tf32(float x) {
    uint32_t r;
    asm("cvt.rna.tf32.f32 %0, %1;" : "=r"(r) : "f"(x));
    return r;
}

__device__ __forceinline__ void mma_tf32(float c[4], uint32_t a0, uint32_t a1,
                                         uint32_t a2, uint32_t a3,
                                         uint32_t b0, uint32_t b1) {
    asm volatile(
        "mma.sync.aligned.m16n8k8.row.col.f32.tf32.tf32.f32 "
        "{%0,%1,%2,%3}, {%4,%5,%6,%7}, {%8,%9}, {%0,%1,%2,%3};"
        : "+f"(c[0]), "+f"(c[1]), "+f"(c[2]), "+f"(c[3])
        : "r"(a0), "r"(a1), "r"(a2), "r"(a3), "r"(b0), "r"(b1));
}

// ---------------------------------------------------------------------------
// K3/K4: C[M,384] = A[M,K] @ B[384,K]^T  (tf32 tensor-core, 128x128 tile, BK=16)
// 8 warps: 2 (M) x 4 (N); warp tile 64x32 = 4x4 m16n8k8 tiles.
// A selection: use_X ? d_X : A_ext.  C selection: c_sel ? d_G2 : d_G1 (+row off).
#define SMS 136   // smem row stride (mod 32 == 8 -> conflict-free frag reads)

__global__ __launch_bounds__(256, 2)
void k_mma_nt(const float* __restrict__ A_ext, int use_X,
              const float* __restrict__ B,
              int c_sel, int c_row_off, int Mrows, int K) {
    __shared__ uint32_t As[16 * SMS];
    __shared__ uint32_t Bs[16 * SMS];

    const float* A = use_X ? d_X : A_ext;
    float* C = (c_sel ? d_G2 : d_G1) + (size_t)c_row_off * G3;

    const int tid  = threadIdx.x;
    const int lane = tid & 31;
    const int w    = tid >> 5;     // 0..7
    const int wm   = w & 1;        // warp row (2 along M)
    const int wn   = w >> 1;       // warp col (4 along N)
    const int m0   = blockIdx.x * 128;
    const int n0   = blockIdx.y * 128;
    const int g    = lane >> 2;    // groupID
    const int tg   = lane & 3;     // thread-in-group

    float acc[4][4][4];
#pragma unroll
    for (int i = 0; i < 4; ++i)
#pragma unroll
        for (int j = 0; j < 4; ++j)
#pragma unroll
            for (int c = 0; c < 4; ++c) acc[i][j][c] = 0.f;

    // per-thread gmem load slots: idx = tid*2+u over 512 float4s (128 rows x 4 groups)
    const int r0 = (tid * 2 + 0) >> 2, c0g = (tid * 2 + 0) & 3;
    const int r1 = (tid * 2 + 1) >> 2, c1g = (tid * 2 + 1) & 3;

    float4 pa0, pa1, pb0, pb1;
    const bool a_ok0 = (m0 + r0) < Mrows;
    const bool a_ok1 = (m0 + r1) < Mrows;
    const float* Ap0 = A + (size_t)(m0 + r0) * K + c0g * 4;
    const float* Ap1 = A + (size_t)(m0 + r1) * K + c1g * 4;
    const float* Bp0 = B + (size_t)(n0 + r0) * K + c0g * 4;
    const float* Bp1 = B + (size_t)(n0 + r1) * K + c1g * 4;

    // prefetch k0 = 0
    pa0 = a_ok0 ? *(const float4*)(Ap0) : make_float4(0, 0, 0, 0);
    pa1 = a_ok1 ? *(const float4*)(Ap1) : make_float4(0, 0, 0, 0);
    pb0 = *(const float4*)(Bp0);
    pb1 = *(const float4*)(Bp1);

    for (int k0 = 0; k0 < K; k0 += 16) {
        // store staged regs -> smem (transposed, tf32-rounded)
        {
            int ka = c0g * 4, kb = c1g * 4;
            As[(ka + 0) * SMS + r0] = f2tf32(pa0.x);
            As[(ka + 1) * SMS + r0] = f2tf32(pa0.y);
            As[(ka + 2) * SMS + r0] = f2tf32(pa0.z);
            As[(ka + 3) * SMS + r0] = f2tf32(pa0.w);
            As[(kb + 0) * SMS + r1] = f2tf32(pa1.x);
            As[(kb + 1) * SMS + r1] = f2tf32(pa1.y);
            As[(kb + 2) * SMS + r1] = f2tf32(pa1.z);
            As[(kb + 3) * SMS + r1] = f2tf32(pa1.w);
            Bs[(ka + 0) * SMS + r0] = f2tf32(pb0.x);
            Bs[(ka + 1) * SMS + r0] = f2tf32(pb0.y);
            Bs[(ka + 2) * SMS + r0] = f2tf32(pb0.z);
            Bs[(ka + 3) * SMS + r0] = f2tf32(pb0.w);
            Bs[(kb + 0) * SMS + r1] = f2tf32(pb1.x);
            Bs[(kb + 1) * SMS + r1] = f2tf32(pb1.y);
            Bs[(kb + 2) * SMS + r1] = f2tf32(pb1.z);
            Bs[(kb + 3) * SMS + r1] = f2tf32(pb1.w);
        }
        __syncthreads();

        // prefetch next chunk while computing this one
        if (k0 + 16 < K) {
            pa0 = a_ok0 ? *(const float4*)(Ap0 + k0 + 16) : make_float4(0, 0, 0, 0);
            pa1 = a_ok1 ? *(const float4*)(Ap1 + k0 + 16) : make_float4(0, 0, 0, 0);
            pb0 = *(const float4*)(Bp0 + k0 + 16);
            pb1 = *(const float4*)(Bp1 + k0 + 16);
        }

#pragma unroll
        for (int kk = 0; kk < 16; kk += 8) {
            uint32_t afr[4][4];
            uint32_t bfr[4][2];
#pragma unroll
            for (int im = 0; im < 4; ++im) {
                int m = wm * 64 + im * 16;
                afr[im][0] = As[(kk + tg) * SMS + m + g];
                afr[im][1] = As[(kk + tg) * SMS + m + g + 8];
                afr[im][2] = As[(kk + tg + 4) * SMS + m + g];
                afr[im][3] = As[(kk + tg + 4) * SMS + m + g + 8];
            }
#pragma unroll
            for (int in_ = 0; in_ < 4; ++in_) {
                int n = wn * 32 + in_ * 8 + g;
                bfr[in_][0] = Bs[(kk + tg) * SMS + n];
                bfr[in_][1] = Bs[(kk + tg + 4) * SMS + n];
            }
#pragma unroll
            for (int im = 0; im < 4; ++im)
#pragma unroll
                for (int in_ = 0; in_ < 4; ++in_)
                    mma_tf32(acc[im][in_], afr[im][0], afr[im][1], afr[im][2],
                             afr[im][3], bfr[in_][0], bfr[in_][1]);
        }
        __syncthreads();
    }

    // epilogue: write C
#pragma unroll
    for (int im = 0; im < 4; ++im) {
#pragma unroll
        for (int in_ = 0; in_ < 4; ++in_) {
            int row = m0 + wm * 64 + im * 16 + g;
            int col = n0 + wn * 32 + in_ * 8 + 2 * tg;
            if (row < Mrows)
                *(float2*)(C + (size_t)row * G3 + col) =
                    make_float2(acc[im][in_][0], acc[im][in_][1]);
            if (row + 8 < Mrows)
                *(float2*)(C + (size_t)(row + 8) * G3 + col) =
                    make_float2(acc[im][in_][2], acc[im][in_][3]);
        }
    }
}

// ---------------------------------------------------------------------------
// K5: GRU gate combine + output
__global__ void k_combine(const float* __restrict__ si, const float* __restrict__ sj,
                          const float* __restrict__ bi, const float* __restrict__ bh,
                          float* __restrict__ out) {
    int r = blockIdx.x;
    int j = threadIdx.x;  // 0..127
    const float* g1 = d_G1 + (size_t)r * G3;
    const float* g2 = d_G2 + (size_t)r * G3;

    float h = (r < NU) ? si[(size_t)r * S + j] : sj[(size_t)(r - NU) * S + j];

    float gir = g1[j]       + bi[j];
    float giz = g1[j + 128] + bi[j + 128];
    float gin = g1[j + 256] + bi[j + 256];
    float ghr = g2[j]       + bh[j];
    float ghz = g2[j + 128] + bh[j + 128];
    float ghn = g2[j + 256] + bh[j + 256];

    float rr = 1.f / (1.f + expf(-(gir + ghr)));
    float zz = 1.f / (1.f + expf(-(giz + ghz)));
    float nn = tanhf(gin + rr * ghn);

    out[(size_t)r * S + j] = (1.f - zz) * nn + zz * h;
}

// ---------------------------------------------------------------------------
extern "C" void kernel_launch(void* const* d_in, const int* in_sizes, int n_in,
                              void* d_out, int out_size) {
    const float* si   = (const float*)d_in[0];
    const float* sj   = (const float*)d_in[1];
    const float* t    = (const float*)d_in[2];
    const float* ef   = (const float*)d_in[3];
    const int*   src  = (const int*)d_in[4];
    const int*   dst  = (const int*)d_in[5];
    const float* Wi   = (const float*)d_in[6];
    const float* Wh   = (const float*)d_in[7];
    const float* bi   = (const float*)d_in[8];
    const float* bh   = (const float*)d_in[9];
    const float* freq = (const float*)d_in[10];
    float* out = (float*)d_out;

    // last-edge reduce
    k_init_last<<<(NU + 255) / 256, 256>>>();
    k_scan_edges<<<(NE + 255) / 256, 256>>>(src, dst);

    // gather winning mails into X
    k_build_x<<<NROWS, 128>>>(si, sj, t, ef, src, dst, freq);

    // G1 = X @ Wi^T   (M=200000, K=512)
    {
        dim3 grid((NROWS + 127) / 128, G3 / 128);
        k_mma_nt<<<grid, 256>>>(nullptr, 1, Wi, 0, 0, NROWS, MDIM);
    }
    // G2 = H @ Wh^T   (two launches: users then items; M=100000, K=128)
    {
        dim3 grid((NU + 127) / 128, G3 / 128);
        k_mma_nt<<<grid, 256>>>(si, 0, Wh, 1, 0,  NU, S);
        k_mma_nt<<<grid, 256>>>(sj, 0, Wh, 1, NU, NI, S);
    }

    // gates + output
    k_combine<<<NROWS, 128>>>(si, sj, bi, bh, out);
}